// round 3
// baseline (speedup 1.0000x reference)
#include <cuda_runtime.h>
#include <cuda_fp16.h>
#include <cstdint>

#define H 8
#define B 4
#define S 2048
#define D 8
#define F 64
#define HB 32            // H*B
#define TILES 32
#define ROWS_CTA 64      // S / TILES
#define WARPS 8
#define RPW (ROWS_CTA / WARPS)   // 8 rows per warp
#define RBLK 4                   // rows in flight per lane

typedef unsigned long long u64;

// Scratch (static __device__, no allocation). All tensors [hb][d][s].
__device__ float g_q [HB * D * S];   // pre-scaled by log2e/sqrt(8)
__device__ float g_kT[HB * D * S];
__device__ float g_vT[HB * D * S];
__device__ float g_cs  [HB * TILES * S];  // per-(hb,tile) weight column sums
__device__ float g_part[HB * D];          // per-hb head sums

__device__ __forceinline__ float ex2f(float x) {
    float y; asm("ex2.approx.ftz.f32 %0, %1;" : "=f"(y) : "f"(x)); return y;
}
__device__ __forceinline__ u64 fma2(u64 a, u64 b, u64 c) {
    u64 d; asm("fma.rn.f32x2 %0, %1, %2, %3;" : "=l"(d) : "l"(a), "l"(b), "l"(c)); return d;
}
__device__ __forceinline__ u64 mul2u(u64 a, u64 b) {
    u64 d; asm("mul.rn.f32x2 %0, %1, %2;" : "=l"(d) : "l"(a), "l"(b)); return d;
}
__device__ __forceinline__ u64 add2u(u64 a, u64 b) {
    u64 d; asm("add.rn.f32x2 %0, %1, %2;" : "=l"(d) : "l"(a), "l"(b)); return d;
}
__device__ __forceinline__ u64 pack2(float lo, float hi) {
    u64 d; asm("mov.b64 %0, {%1, %2};" : "=l"(d) : "f"(lo), "f"(hi)); return d;
}
__device__ __forceinline__ float2 unpk2(u64 a) {
    float2 r; asm("mov.b64 {%0, %1}, %2;" : "=f"(r.x), "=f"(r.y) : "l"(a)); return r;
}

// ---------------------------------------------------------------------------
// Kernel 1: QKV projection. grid 1024 x 192 thr; 8 (b,s) rows per block.
// W staged in padded smem (conflict-free); 52KB smem -> 4 CTAs/SM, 24 warps/SM.
// Outputs [hb][d][s], q pre-scaled by log2e/sqrt(8), contiguous float4 stores.
// ---------------------------------------------------------------------------
#define K1_ROWS 8
#define WPAD 520
__global__ void __launch_bounds__(192) qkv_kernel(
    const float* __restrict__ x,
    const float* __restrict__ Wq,
    const float* __restrict__ Wk,
    const float* __restrict__ Wv)
{
    extern __shared__ float k1sm[];
    float* xs = k1sm;                  // 512 floats
    float* Ws = k1sm + 512;            // 3 * 8 * 520 = 12480 floats

    const int tid = threadIdx.x;
    const int rowbase = blockIdx.x * K1_ROWS;

    for (int i = tid; i < K1_ROWS * 64; i += 192)
        xs[i] = x[(size_t)rowbase * 64 + i];
    const float* Wsrc[3] = {Wq, Wk, Wv};
#pragma unroll
    for (int t3 = 0; t3 < 3; ++t3) {
        const float* W = Wsrc[t3];
        for (int i = tid; i < 4096; i += 192) {
            const int h = i >> 9, rem = i & 511;
            Ws[t3 * (8 * WPAD) + h * WPAD + rem] = W[i];
        }
    }
    __syncthreads();

    const int tensor = tid / 64;     // uniform per warp
    const int c = tid % 64;
    const int h = c >> 3, d = c & 7;
    const float* Wc = Ws + tensor * (8 * WPAD) + h * WPAD;

    float acc[K1_ROWS];
#pragma unroll
    for (int r = 0; r < K1_ROWS; ++r) acc[r] = 0.f;

#pragma unroll
    for (int f4 = 0; f4 < 16; ++f4) {
        const float w0 = Wc[(f4 * 4 + 0) * 8 + d];
        const float w1 = Wc[(f4 * 4 + 1) * 8 + d];
        const float w2 = Wc[(f4 * 4 + 2) * 8 + d];
        const float w3 = Wc[(f4 * 4 + 3) * 8 + d];
#pragma unroll
        for (int r = 0; r < K1_ROWS; ++r) {
            float4 xv = *(const float4*)&xs[r * 64 + f4 * 4];  // broadcast
            acc[r] = fmaf(xv.x, w0, fmaf(xv.y, w1, fmaf(xv.z, w2, fmaf(xv.w, w3, acc[r]))));
        }
    }

    const int b  = rowbase >> 11;
    const int s0 = rowbase & 2047;
    const int hb = h * 4 + b;
    const float QS = 0.51006975f;  // log2(e)/sqrt(8)
    float* dst;
    if (tensor == 0) {
        dst = g_q + ((size_t)hb * 8 + d) * S + s0;
#pragma unroll
        for (int i = 0; i < K1_ROWS / 4; ++i) {
            float4 v = make_float4(acc[4*i]*QS, acc[4*i+1]*QS, acc[4*i+2]*QS, acc[4*i+3]*QS);
            *(float4*)(dst + 4 * i) = v;
        }
    } else {
        dst = (tensor == 1 ? g_kT : g_vT) + ((size_t)hb * 8 + d) * S + s0;
#pragma unroll
        for (int i = 0; i < K1_ROWS / 4; ++i) {
            float4 v = make_float4(acc[4*i], acc[4*i+1], acc[4*i+2], acc[4*i+3]);
            *(float4*)(dst + 4 * i) = v;
        }
    }
}

// ---------------------------------------------------------------------------
// Kernel 2: attention weights. grid (TILES, HB), 256 threads (8 warps).
// No PV: only weight writes + per-column sums (sum_s heads folded via
// head_sum[d] = sum_t colsum[t]*v[t][d] computed later).
// smem: kT[8][2048] (64KB) + q[8][64] (2KB) + e fp16 [8 warps][4 rows][2048]
// (128KB). Column sums accumulate in 32 packed f32x2 regs per lane; reduced
// across warps via smem (reusing e region) deterministically.
// ---------------------------------------------------------------------------
__global__ void __launch_bounds__(256, 1) attn_kernel(float* __restrict__ wout)
{
    extern __shared__ float sm[];
    float*  kS  = sm;                      // 16384 floats
    float*  qS  = sm + 16384;              // 512 floats [d][64]
    __half* eS  = (__half*)(sm + 16896);   // 65536 halfs (32768 floats)
    float*  csS = sm + 16896;              // reuse of e region after sync: [8][2048]

    const int tid  = threadIdx.x;
    const int lane = tid & 31;
    const int wrp  = tid >> 5;
    const int tile = blockIdx.x;
    const int hb   = blockIdx.y;

    {
        const float4* k4 = (const float4*)(g_kT + (size_t)hb * D * S);
        float4* kd = (float4*)kS;
#pragma unroll
        for (int i = 0; i < 16; ++i) kd[tid + 256 * i] = k4[tid + 256 * i];
        for (int i = tid; i < ROWS_CTA * D; i += 256) {
            const int d = i >> 6, sl = i & 63;
            qS[i] = g_q[((size_t)hb * 8 + d) * S + tile * ROWS_CTA + sl];
        }
    }
    __syncthreads();

    u64 cs2[32];
#pragma unroll
    for (int i = 0; i < 32; ++i) cs2[i] = 0ull;

    __half* eb = eS + (size_t)wrp * (RBLK * S);

#pragma unroll 1
    for (int g = 0; g < RPW / RBLK; ++g) {
        const int rl = wrp * RPW + g * RBLK;

        u64 q2[RBLK][8];
#pragma unroll
        for (int r = 0; r < RBLK; ++r)
#pragma unroll
            for (int d = 0; d < 8; ++d) {
                float q = qS[d * ROWS_CTA + rl + r];
                q2[r][d] = pack2(q, q);
            }

        u64 ls2[RBLK];
#pragma unroll
        for (int r = 0; r < RBLK; ++r) ls2[r] = 0ull;

#pragma unroll 1
        for (int c = 0; c < 16; ++c) {
            const int col = c * 128 + lane * 4;

            u64 k2[8][2];
#pragma unroll
            for (int d = 0; d < 8; ++d) {
                ulonglong2 t = *(const ulonglong2*)(kS + d * S + col);
                k2[d][0] = t.x; k2[d][1] = t.y;
            }

#pragma unroll
            for (int r = 0; r < RBLK; ++r) {
                __half2 hv[2];
#pragma unroll
                for (int p = 0; p < 2; ++p) {
                    u64 s2 = mul2u(q2[r][0], k2[0][p]);
#pragma unroll
                    for (int d = 1; d < 8; ++d) s2 = fma2(q2[r][d], k2[d][p], s2);
                    float2 sv = unpk2(s2);
                    float elo = ex2f(sv.x), ehi = ex2f(sv.y);
                    ls2[r] = add2u(ls2[r], pack2(elo, ehi));
                    hv[p] = __floats2half2_rn(elo, ehi);
                }
                uint2 st2;
                st2.x = *(unsigned*)&hv[0];
                st2.y = *(unsigned*)&hv[1];
                *(uint2*)(eb + r * S + col) = st2;
            }
        }

        // row denominators (full row lives in this warp)
        float inv[RBLK];
#pragma unroll
        for (int r = 0; r < RBLK; ++r) {
            float2 lv = unpk2(ls2[r]);
            float v = lv.x + lv.y;
#pragma unroll
            for (int o = 16; o > 0; o >>= 1) v += __shfl_xor_sync(0xffffffffu, v, o);
            inv[r] = 1.0f / v;
        }

        // normalize + stream out + accumulate column sums
        const size_t wb = ((size_t)hb * S + tile * ROWS_CTA + rl) * S;
#pragma unroll
        for (int r = 0; r < RBLK; ++r) {
            const u64 iv2 = pack2(inv[r], inv[r]);
            float* wr = wout + wb + (size_t)r * S;
            const __half* er = eb + r * S;
#pragma unroll 1
            for (int c = 0; c < 16; ++c) {
                const int col = c * 128 + lane * 4;
                uint2 raw = *(const uint2*)(er + col);
                __half2 a  = *(__half2*)&raw.x;
                __half2 b2 = *(__half2*)&raw.y;
                float2 fa = __half22float2(a);
                float2 fb = __half22float2(b2);
                u64 w0 = mul2u(pack2(fa.x, fa.y), iv2);
                u64 w1 = mul2u(pack2(fb.x, fb.y), iv2);
                cs2[2*c+0] = add2u(cs2[2*c+0], w0);
                cs2[2*c+1] = add2u(cs2[2*c+1], w1);
                asm volatile("st.global.cs.v2.b64 [%0], {%1, %2};"
                             :: "l"(wr + col), "l"(w0), "l"(w1) : "memory");
            }
        }
    }

    // cross-warp column-sum reduction (deterministic), reusing e region
    __syncthreads();
    {
        float* csW = csS + wrp * S;
#pragma unroll
        for (int c = 0; c < 16; ++c) {
            const int col = c * 128 + lane * 4;
            ulonglong2 t; t.x = cs2[2*c]; t.y = cs2[2*c+1];
            *(ulonglong2*)(csW + col) = t;
        }
    }
    __syncthreads();
    {
        float* dst = g_cs + ((size_t)hb * TILES + tile) * S;
        const int j0 = tid * 8;
#pragma unroll
        for (int jj = 0; jj < 2; ++jj) {
            float4 s = make_float4(0.f, 0.f, 0.f, 0.f);
#pragma unroll
            for (int w = 0; w < 8; ++w) {
                float4 t = *(const float4*)(csS + w * S + j0 + jj * 4);
                s.x += t.x; s.y += t.y; s.z += t.z; s.w += t.w;
            }
            *(float4*)(dst + j0 + jj * 4) = s;
        }
    }
}

// ---------------------------------------------------------------------------
// Kernel 3: per-hb: cs_total[t] = sum_tile g_cs; head_sum[d] = sum_t cs*v[d][t]
// ---------------------------------------------------------------------------
__global__ void __launch_bounds__(256) colsum_v_kernel()
{
    const int hb  = blockIdx.x;
    const int tid = threadIdx.x;
    const int lane = tid & 31, wrp = tid >> 5;
    const int t0 = tid * 8;

    float cs[8];
#pragma unroll
    for (int i = 0; i < 8; ++i) cs[i] = 0.f;
    for (int tl = 0; tl < TILES; ++tl) {
        const float* src = g_cs + ((size_t)hb * TILES + tl) * S + t0;
        float4 a = *(const float4*)(src);
        float4 b = *(const float4*)(src + 4);
        cs[0]+=a.x; cs[1]+=a.y; cs[2]+=a.z; cs[3]+=a.w;
        cs[4]+=b.x; cs[5]+=b.y; cs[6]+=b.z; cs[7]+=b.w;
    }

    float p[8];
#pragma unroll
    for (int d = 0; d < 8; ++d) {
        const float* vr = g_vT + ((size_t)hb * 8 + d) * S + t0;
        float4 a = *(const float4*)(vr);
        float4 b = *(const float4*)(vr + 4);
        float s = cs[0]*a.x + cs[1]*a.y + cs[2]*a.z + cs[3]*a.w
                + cs[4]*b.x + cs[5]*b.y + cs[6]*b.z + cs[7]*b.w;
        p[d] = s;
    }

    __shared__ float red[8][8];
#pragma unroll
    for (int d = 0; d < 8; ++d) {
        float v = p[d];
#pragma unroll
        for (int o = 16; o > 0; o >>= 1) v += __shfl_xor_sync(0xffffffffu, v, o);
        p[d] = v;
    }
    if (lane == 0) {
#pragma unroll
        for (int d = 0; d < 8; ++d) red[wrp][d] = p[d];
    }
    __syncthreads();
    if (tid < 8) {
        float s = 0.f;
#pragma unroll
        for (int w = 0; w < 8; ++w) s += red[w][tid];
        g_part[hb * 8 + tid] = s;
    }
}

// ---------------------------------------------------------------------------
// Kernel 4: out[b][f] = sum_{h,d} head_sum[b][h*8+d] * Wo[h*8+d][f]
// ---------------------------------------------------------------------------
__global__ void __launch_bounds__(256) out_kernel(
    const float* __restrict__ Wo, float* __restrict__ out)
{
    __shared__ float hs[256];
    const int t = threadIdx.x;
    {
        const int b = t >> 6, j = t & 63;
        const int h = j >> 3, d = j & 7;
        hs[t] = g_part[(h * 4 + b) * 8 + d];
    }
    __syncthreads();
    const int b = t >> 6, f = t & 63;
    float a = 0.f;
#pragma unroll
    for (int j = 0; j < 64; ++j)
        a = fmaf(hs[b * 64 + j], Wo[j * 64 + f], a);
    out[b * 64 + f] = a;
}

// ---------------------------------------------------------------------------
extern "C" void kernel_launch(void* const* d_in, const int* in_sizes, int n_in,
                              void* d_out, int out_size)
{
    const float* x  = (const float*)d_in[0];
    const float* Wq = (const float*)d_in[1];
    const float* Wk = (const float*)d_in[2];
    const float* Wv = (const float*)d_in[3];
    const float* Wo = (const float*)d_in[4];
    float* out = (float*)d_out;

    const long long WELEMS = (long long)HB * S * S;  // 134217728
    float* wout = out;
    bool has_sum = false;
    if ((long long)out_size >= WELEMS + 256) {  // [sum(256) | weights]
        wout = out + 256;
        has_sum = true;
    }

    const int k1_smem = (512 + 3 * 8 * WPAD) * 4;   // 51968
    const int k2_smem = (16896 + 32768) * 4;        // 198656
    cudaFuncSetAttribute(qkv_kernel,  cudaFuncAttributeMaxDynamicSharedMemorySize, k1_smem);
    cudaFuncSetAttribute(attn_kernel, cudaFuncAttributeMaxDynamicSharedMemorySize, k2_smem);

    qkv_kernel<<<(B * S) / K1_ROWS, 192, k1_smem>>>(x, Wq, Wk, Wv);
    attn_kernel<<<dim3(TILES, HB), 256, k2_smem>>>(wout);
    if (has_sum) {
        colsum_v_kernel<<<HB, 256>>>();
        out_kernel<<<1, 256>>>(Wo, out);
    }
}

// round 4
// speedup vs baseline: 1.3476x; 1.3476x over previous
#include <cuda_runtime.h>
#include <cstdint>

#define H 8
#define B 4
#define S 2048
#define D 8
#define F 64
#define HB 32
#define TILES 64
#define ROWS_CTA 32      // S / TILES
#define WARPS 4
#define RPW (ROWS_CTA / WARPS)   // 8 rows per warp

typedef unsigned long long u64;

// Scratch (static __device__, no allocation). q/k/v laid out [hb][d][s].
__device__ float g_q [HB * D * S];        // pre-scaled by log2e/sqrt(8)
__device__ float g_kT[HB * D * S];
__device__ float g_vT[HB * D * S];
__device__ float g_cs  [HB * TILES * S];  // per-(hb,tile) weight column sums
__device__ float g_part[HB * D];          // per-hb head sums

__device__ __forceinline__ float ex2f(float x) {
    float y; asm("ex2.approx.ftz.f32 %0, %1;" : "=f"(y) : "f"(x)); return y;
}
__device__ __forceinline__ u64 fma2(u64 a, u64 b, u64 c) {
    u64 d; asm("fma.rn.f32x2 %0, %1, %2, %3;" : "=l"(d) : "l"(a), "l"(b), "l"(c)); return d;
}
__device__ __forceinline__ u64 mul2u(u64 a, u64 b) {
    u64 d; asm("mul.rn.f32x2 %0, %1, %2;" : "=l"(d) : "l"(a), "l"(b)); return d;
}
__device__ __forceinline__ u64 add2u(u64 a, u64 b) {
    u64 d; asm("add.rn.f32x2 %0, %1, %2;" : "=l"(d) : "l"(a), "l"(b)); return d;
}
__device__ __forceinline__ u64 pack2(float lo, float hi) {
    u64 d; asm("mov.b64 %0, {%1, %2};" : "=l"(d) : "f"(lo), "f"(hi)); return d;
}
__device__ __forceinline__ float2 unpk2(u64 a) {
    float2 r; asm("mov.b64 {%0, %1}, %2;" : "=f"(r.x), "=f"(r.y) : "l"(a)); return r;
}

// ---------------------------------------------------------------------------
// Kernel 1: QKV projection. grid 512 x 192 thr; 16 rows/block.
// Per-thread W column kept in registers (64 floats); x rows staged in smem.
// Outputs [hb][d][s]; q pre-scaled by log2e/sqrt(8).
// ---------------------------------------------------------------------------
#define K1_ROWS 16
__global__ void __launch_bounds__(192) qkv_kernel(
    const float* __restrict__ x,
    const float* __restrict__ Wq,
    const float* __restrict__ Wk,
    const float* __restrict__ Wv)
{
    __shared__ float xs[K1_ROWS * 64];
    const int tid = threadIdx.x;
    const int rowbase = blockIdx.x * K1_ROWS;

    for (int i = tid; i < K1_ROWS * 64; i += 192)
        xs[i] = x[(size_t)rowbase * 64 + i];

    const int tensor = tid / 64;   // uniform per warp pair
    const int c = tid % 64;
    const int h = c >> 3, d = c & 7;
    const float* W = (tensor == 0) ? Wq : ((tensor == 1) ? Wk : Wv);

    float w[64];
#pragma unroll
    for (int f = 0; f < 64; ++f) w[f] = __ldg(&W[((size_t)h * 64 + f) * 8 + d]);

    __syncthreads();

    float acc[K1_ROWS];
#pragma unroll
    for (int r = 0; r < K1_ROWS; ++r) acc[r] = 0.f;

#pragma unroll
    for (int f4 = 0; f4 < 16; ++f4) {
#pragma unroll
        for (int r = 0; r < K1_ROWS; ++r) {
            float4 xv = *(const float4*)&xs[r * 64 + f4 * 4];  // broadcast
            acc[r] = fmaf(xv.x, w[4*f4+0], fmaf(xv.y, w[4*f4+1],
                     fmaf(xv.z, w[4*f4+2], fmaf(xv.w, w[4*f4+3], acc[r]))));
        }
    }

    const int b  = rowbase >> 11;
    const int s0 = rowbase & 2047;
    const int hb = h * 4 + b;
    const float QS = 0.51006975f;  // log2(e)/sqrt(8)
    float* dst;
    if (tensor == 0) {
        dst = g_q + ((size_t)hb * 8 + d) * S + s0;
#pragma unroll
        for (int i = 0; i < K1_ROWS / 4; ++i)
            *(float4*)(dst + 4 * i) = make_float4(acc[4*i]*QS, acc[4*i+1]*QS,
                                                  acc[4*i+2]*QS, acc[4*i+3]*QS);
    } else {
        dst = (tensor == 1 ? g_kT : g_vT) + ((size_t)hb * 8 + d) * S + s0;
#pragma unroll
        for (int i = 0; i < K1_ROWS / 4; ++i)
            *(float4*)(dst + 4 * i) = make_float4(acc[4*i], acc[4*i+1],
                                                  acc[4*i+2], acc[4*i+3]);
    }
}

// ---------------------------------------------------------------------------
// Kernel 2: attention weights, recompute style (no e-buffer).
// grid (TILES=64, HB=32), 128 threads, smem = k[8][2048] + q[8][32] = ~65KB
// => 3 CTAs/SM. Pass 1: row denominators (registers only). Pass 2: recompute
// exp, normalize, stream fp32 weights (__stcs), accumulate column sums in
// packed f32x2 regs; cross-warp colsum reduction reuses kS after a sync.
// ---------------------------------------------------------------------------
__global__ void __launch_bounds__(128, 3) attn_kernel(float* __restrict__ wout)
{
    extern __shared__ float sm[];
    float* kS = sm;              // 16384 floats
    float* qS = sm + 16384;      // 256 floats [d][32]

    const int tid  = threadIdx.x;
    const int lane = tid & 31;
    const int wrp  = tid >> 5;
    const int tile = blockIdx.x;
    const int hb   = blockIdx.y;

    {
        const float4* k4 = (const float4*)(g_kT + (size_t)hb * D * S);
        float4* kd = (float4*)kS;
#pragma unroll
        for (int i = 0; i < 32; ++i) kd[tid + 128 * i] = k4[tid + 128 * i];
        if (tid < ROWS_CTA * D / 4) {
            // q tile [d][32] as float4 along s
            const int d = tid >> 3, sl = (tid & 7) * 4;
            *(float4*)&qS[d * ROWS_CTA + sl] =
                *(const float4*)&g_q[((size_t)hb * 8 + d) * S + tile * ROWS_CTA + sl];
        }
    }
    __syncthreads();

    // ---------------- pass 1: denominators for this warp's 8 rows ----------
    float inv_all[RPW];
#pragma unroll 1
    for (int g = 0; g < RPW / 4; ++g) {
        const int rl = wrp * RPW + g * 4;
        u64 q2[4][8];
#pragma unroll
        for (int r = 0; r < 4; ++r)
#pragma unroll
            for (int d = 0; d < 8; ++d) {
                float q = qS[d * ROWS_CTA + rl + r];
                q2[r][d] = pack2(q, q);
            }
        u64 ls2[4];
#pragma unroll
        for (int r = 0; r < 4; ++r) ls2[r] = 0ull;

#pragma unroll 1
        for (int c = 0; c < 16; ++c) {
            const int col = c * 128 + lane * 4;
            u64 k2[8][2];
#pragma unroll
            for (int d = 0; d < 8; ++d) {
                ulonglong2 t = *(const ulonglong2*)(kS + d * S + col);
                k2[d][0] = t.x; k2[d][1] = t.y;
            }
#pragma unroll
            for (int r = 0; r < 4; ++r)
#pragma unroll
                for (int p = 0; p < 2; ++p) {
                    u64 s2 = mul2u(q2[r][0], k2[0][p]);
#pragma unroll
                    for (int d = 1; d < 8; ++d) s2 = fma2(q2[r][d], k2[d][p], s2);
                    float2 sv = unpk2(s2);
                    ls2[r] = add2u(ls2[r], pack2(ex2f(sv.x), ex2f(sv.y)));
                }
        }
#pragma unroll
        for (int r = 0; r < 4; ++r) {
            float2 lv = unpk2(ls2[r]);
            float v = lv.x + lv.y;
#pragma unroll
            for (int o = 16; o > 0; o >>= 1) v += __shfl_xor_sync(0xffffffffu, v, o);
            inv_all[g * 4 + r] = 1.0f / v;
        }
    }

    // ---------------- pass 2: recompute, normalize, write, colsum ----------
    u64 cs2[32];
#pragma unroll
    for (int i = 0; i < 32; ++i) cs2[i] = 0ull;

#pragma unroll 1
    for (int g = 0; g < RPW / 2; ++g) {
        const int rl = wrp * RPW + g * 2;
        u64 q2[2][8];
        u64 iv2[2];
#pragma unroll
        for (int r = 0; r < 2; ++r) {
#pragma unroll
            for (int d = 0; d < 8; ++d) {
                float q = qS[d * ROWS_CTA + rl + r];
                q2[r][d] = pack2(q, q);
            }
            float iv = inv_all[g * 2 + r];
            iv2[r] = pack2(iv, iv);
        }
        const size_t wb = ((size_t)hb * S + tile * ROWS_CTA + rl) * S;

#pragma unroll 1
        for (int c = 0; c < 16; ++c) {
            const int col = c * 128 + lane * 4;
            u64 k2[8][2];
#pragma unroll
            for (int d = 0; d < 8; ++d) {
                ulonglong2 t = *(const ulonglong2*)(kS + d * S + col);
                k2[d][0] = t.x; k2[d][1] = t.y;
            }
#pragma unroll
            for (int r = 0; r < 2; ++r) {
                u64 w2[2];
#pragma unroll
                for (int p = 0; p < 2; ++p) {
                    u64 s2 = mul2u(q2[r][0], k2[0][p]);
#pragma unroll
                    for (int d = 1; d < 8; ++d) s2 = fma2(q2[r][d], k2[d][p], s2);
                    float2 sv = unpk2(s2);
                    u64 e2 = pack2(ex2f(sv.x), ex2f(sv.y));
                    w2[p] = mul2u(e2, iv2[r]);
                    cs2[2 * c + p] = add2u(cs2[2 * c + p], w2[p]);
                }
                float2 a = unpk2(w2[0]);
                float2 b = unpk2(w2[1]);
                __stcs((float4*)(wout + wb + (size_t)r * S + col),
                       make_float4(a.x, a.y, b.x, b.y));
            }
        }
    }

    // ---------------- cross-warp colsum reduction (reuse kS) ---------------
    __syncthreads();
    {
        float* csW = kS + wrp * S;
#pragma unroll
        for (int c = 0; c < 16; ++c) {
            const int col = c * 128 + lane * 4;
            ulonglong2 t; t.x = cs2[2 * c]; t.y = cs2[2 * c + 1];
            *(ulonglong2*)(csW + col) = t;
        }
    }
    __syncthreads();
    {
        float* dst = g_cs + ((size_t)hb * TILES + tile) * S;
        const int j0 = tid * 16;
#pragma unroll
        for (int jj = 0; jj < 4; ++jj) {
            float4 s = make_float4(0.f, 0.f, 0.f, 0.f);
#pragma unroll
            for (int w = 0; w < 4; ++w) {
                float4 t = *(const float4*)(kS + w * S + j0 + jj * 4);
                s.x += t.x; s.y += t.y; s.z += t.z; s.w += t.w;
            }
            *(float4*)(dst + j0 + jj * 4) = s;
        }
    }
}

// ---------------------------------------------------------------------------
// Kernel 3: per-hb: cs_total[t] = sum_tile g_cs; head_sum[d] = sum_t cs*v[d][t]
// ---------------------------------------------------------------------------
__global__ void __launch_bounds__(256) colsum_v_kernel()
{
    const int hb  = blockIdx.x;
    const int tid = threadIdx.x;
    const int lane = tid & 31, wrp = tid >> 5;
    const int t0 = tid * 8;

    float cs[8];
#pragma unroll
    for (int i = 0; i < 8; ++i) cs[i] = 0.f;
#pragma unroll 1
    for (int tl = 0; tl < TILES; ++tl) {
        const float* src = g_cs + ((size_t)hb * TILES + tl) * S + t0;
        float4 a = *(const float4*)(src);
        float4 b = *(const float4*)(src + 4);
        cs[0]+=a.x; cs[1]+=a.y; cs[2]+=a.z; cs[3]+=a.w;
        cs[4]+=b.x; cs[5]+=b.y; cs[6]+=b.z; cs[7]+=b.w;
    }

    float p[8];
#pragma unroll
    for (int d = 0; d < 8; ++d) {
        const float* vr = g_vT + ((size_t)hb * 8 + d) * S + t0;
        float4 a = *(const float4*)(vr);
        float4 b = *(const float4*)(vr + 4);
        p[d] = cs[0]*a.x + cs[1]*a.y + cs[2]*a.z + cs[3]*a.w
             + cs[4]*b.x + cs[5]*b.y + cs[6]*b.z + cs[7]*b.w;
    }

    __shared__ float red[8][8];
#pragma unroll
    for (int d = 0; d < 8; ++d) {
        float v = p[d];
#pragma unroll
        for (int o = 16; o > 0; o >>= 1) v += __shfl_xor_sync(0xffffffffu, v, o);
        p[d] = v;
    }
    if (lane == 0) {
#pragma unroll
        for (int d = 0; d < 8; ++d) red[wrp][d] = p[d];
    }
    __syncthreads();
    if (tid < 8) {
        float s = 0.f;
#pragma unroll
        for (int w = 0; w < 8; ++w) s += red[w][tid];
        g_part[hb * 8 + tid] = s;
    }
}

// ---------------------------------------------------------------------------
// Kernel 4: out[b][f] = sum_{h,d} head_sum[b][h*8+d] * Wo[h*8+d][f]
// ---------------------------------------------------------------------------
__global__ void __launch_bounds__(256) out_kernel(
    const float* __restrict__ Wo, float* __restrict__ out)
{
    __shared__ float hs[256];
    const int t = threadIdx.x;
    {
        const int b = t >> 6, j = t & 63;
        const int h = j >> 3, d = j & 7;
        hs[t] = g_part[(h * 4 + b) * 8 + d];
    }
    __syncthreads();
    const int b = t >> 6, f = t & 63;
    float a = 0.f;
#pragma unroll
    for (int j = 0; j < 64; ++j)
        a = fmaf(hs[b * 64 + j], Wo[j * 64 + f], a);
    out[b * 64 + f] = a;
}

// ---------------------------------------------------------------------------
extern "C" void kernel_launch(void* const* d_in, const int* in_sizes, int n_in,
                              void* d_out, int out_size)
{
    const float* x  = (const float*)d_in[0];
    const float* Wq = (const float*)d_in[1];
    const float* Wk = (const float*)d_in[2];
    const float* Wv = (const float*)d_in[3];
    const float* Wo = (const float*)d_in[4];
    float* out = (float*)d_out;

    const long long WELEMS = (long long)HB * S * S;  // 134217728
    float* wout = out;
    bool has_sum = false;
    if ((long long)out_size >= WELEMS + 256) {  // [sum(256) | weights]
        wout = out + 256;
        has_sum = true;
    }

    const int k2_smem = (16384 + 256) * 4;   // 66560
    cudaFuncSetAttribute(attn_kernel, cudaFuncAttributeMaxDynamicSharedMemorySize, k2_smem);

    qkv_kernel<<<(B * S) / K1_ROWS, 192>>>(x, Wq, Wk, Wv);
    attn_kernel<<<dim3(TILES, HB), 128, k2_smem>>>(wout);
    if (has_sum) {
        colsum_v_kernel<<<HB, 256>>>();
        out_kernel<<<1, 256>>>(Wo, out);
    }
}